// round 8
// baseline (speedup 1.0000x reference)
#include <cuda_runtime.h>
#include <cstdint>

#define BI 128
#define BT 128
#define RR 36
#define WW 50
#define DD 256
#define ILAMB 20.0f     // 1/0.05
#define EPSV 1e-6f

#define IP 2            // imgs per block
#define JP 2            // caps per block
#define NPAIR 4         // IP*JP, 2 warps per pair
#define KC 32           // K-chunk
#define NCHUNK (DD / KC)   // 8
#define MT 3            // 48 rows padded
#define NT 7            // 56 cols padded
#define NKS (KC / 8)    // 4 k-steps per chunk

// Pre-baked fragment-quad layouts in gmem (ks-major => chunk-contiguous):
// A quad (16B) at ((ks*3+mt)*32 + gid*4+tig): {A[r][k], A[r+8][k], A[r][k+4], A[r+8][k+4]}
// B pair (8B)  at ((ks*7+nt)*32 + gid*4+tig): {B[n][k], B[n][k+4]}
#define A_IMG_FLOATS (32 * MT * 128)    // 12288 per image
#define B_CAP_FLOATS (32 * NT * 64)     // 14336 per cap
#define A_CHUNK_FLOATS (NKS * MT * 128) // 1536 per image per chunk
#define B_CHUNK_FLOATS (NKS * NT * 64)  // 1792 per cap per chunk
#define A_REG_FLOATS (IP * A_CHUNK_FLOATS)  // 3072
#define B_REG_FLOATS (JP * B_CHUNK_FLOATS)  // 3584
#define BUF_FLOATS (A_REG_FLOATS + B_REG_FLOATS)  // 6656
#define BUF_BYTES (BUF_FLOATS * 4)                // 26624

// Sinkhorn scratch (reuses the two staging buffers after GEMM)
#define KW 57                           // >= WW, odd: conflict-free col walks
#define KS_STRIDE (RR * KW)             // 2052
#define AL_OFF (NPAIR * KS_STRIDE)      // 8208
#define BE_OFF (AL_OFF + NPAIR * RR)    // 8352
#define RS_OFF (BE_OFF + NPAIR * WW)    // 8552 (+8 reduce slots = 8560)

#define SMEM_FLOATS (2 * BUF_FLOATS)    // 13312 > 8560
#define SMEM_BYTES (SMEM_FLOATS * 4)    // 53248

#define NORM_SMEM_BYTES (B_CAP_FLOATS * 4)   // 57344 (max of A/B block)

__device__ float g_aq[BI * A_IMG_FLOATS];
__device__ float g_bq[BT * B_CAP_FLOATS];

__device__ __forceinline__ unsigned f2tf32(float x) {
    unsigned r;
    asm("cvt.rna.tf32.f32 %0, %1;" : "=r"(r) : "f"(x));
    return r;
}

__device__ __forceinline__ void cp16(uint32_t dst, const float* src) {
    asm volatile("cp.async.cg.shared.global [%0], [%1], 16;\n"
                 :: "r"(dst), "l"(src));
}

#define PAIR_BAR(p) asm volatile("bar.sync %0, %1;" :: "r"(1 + (p)), "r"(64) : "memory")

// ---------------------------------------------------------------------------
// Kernel 1: L2-normalize, round to tf32, build fragment-quad layout in smem,
// dump coalesced. One block per image (b < BI) or cap (b >= BI).
// ---------------------------------------------------------------------------
__global__ __launch_bounds__(256)
void norm_kernel(const float* __restrict__ imgs,
                 const float* __restrict__ caps) {
    extern __shared__ float sm[];
    const int b = blockIdx.x;
    const int tid = threadIdx.x;
    const int lane = tid & 31;   // = ks block (k = 8*lane .. 8*lane+7)
    const int wrp = tid >> 5;

    if (b < BI) {
        // ---- image b : 48 padded rows ----
        for (int r = wrp; r < 48; r += 8) {
            float vals[8];
            if (r < RR) {
                const float4* s4 = reinterpret_cast<const float4*>(
                    imgs + ((size_t)b * RR + r) * DD);
                float4 v0 = s4[2 * lane], v1 = s4[2 * lane + 1];
                float ss = v0.x * v0.x + v0.y * v0.y + v0.z * v0.z + v0.w * v0.w
                         + v1.x * v1.x + v1.y * v1.y + v1.z * v1.z + v1.w * v1.w;
#pragma unroll
                for (int o = 16; o > 0; o >>= 1)
                    ss += __shfl_xor_sync(0xffffffffu, ss, o);
                float inv = 1.0f / fmaxf(sqrtf(ss), 1e-8f);
                vals[0] = __uint_as_float(f2tf32(v0.x * inv));
                vals[1] = __uint_as_float(f2tf32(v0.y * inv));
                vals[2] = __uint_as_float(f2tf32(v0.z * inv));
                vals[3] = __uint_as_float(f2tf32(v0.w * inv));
                vals[4] = __uint_as_float(f2tf32(v1.x * inv));
                vals[5] = __uint_as_float(f2tf32(v1.y * inv));
                vals[6] = __uint_as_float(f2tf32(v1.z * inv));
                vals[7] = __uint_as_float(f2tf32(v1.w * inv));
            } else {
#pragma unroll
                for (int y = 0; y < 8; ++y) vals[y] = 0.0f;
            }
            int mt = r >> 4, x = r & 15, g = x & 7, hi = x >> 3;
#pragma unroll
            for (int y = 0; y < 8; ++y) {
                int tg = y & 3, khi = y >> 2;
                sm[((lane * 3 + mt) * 32 + g * 4 + tg) * 4 + khi * 2 + hi] = vals[y];
            }
        }
        __syncthreads();
        float4* dst = reinterpret_cast<float4*>(g_aq + (size_t)b * A_IMG_FLOATS);
        const float4* src = reinterpret_cast<const float4*>(sm);
#pragma unroll
        for (int s = 0; s < A_IMG_FLOATS / 4 / 256; ++s)
            dst[tid + s * 256] = src[tid + s * 256];
    } else {
        // ---- cap j : 56 padded rows ----
        const int j = b - BI;
        for (int w = wrp; w < 56; w += 8) {
            float vals[8];
            if (w < WW) {
                const float4* s4 = reinterpret_cast<const float4*>(
                    caps + ((size_t)j * WW + w) * DD);
                float4 v0 = s4[2 * lane], v1 = s4[2 * lane + 1];
                float ss = v0.x * v0.x + v0.y * v0.y + v0.z * v0.z + v0.w * v0.w
                         + v1.x * v1.x + v1.y * v1.y + v1.z * v1.z + v1.w * v1.w;
#pragma unroll
                for (int o = 16; o > 0; o >>= 1)
                    ss += __shfl_xor_sync(0xffffffffu, ss, o);
                float inv = 1.0f / fmaxf(sqrtf(ss), 1e-8f);
                vals[0] = __uint_as_float(f2tf32(v0.x * inv));
                vals[1] = __uint_as_float(f2tf32(v0.y * inv));
                vals[2] = __uint_as_float(f2tf32(v0.z * inv));
                vals[3] = __uint_as_float(f2tf32(v0.w * inv));
                vals[4] = __uint_as_float(f2tf32(v1.x * inv));
                vals[5] = __uint_as_float(f2tf32(v1.y * inv));
                vals[6] = __uint_as_float(f2tf32(v1.z * inv));
                vals[7] = __uint_as_float(f2tf32(v1.w * inv));
            } else {
#pragma unroll
                for (int y = 0; y < 8; ++y) vals[y] = 0.0f;
            }
            int nt = w >> 3, g = w & 7;
#pragma unroll
            for (int y = 0; y < 8; ++y) {
                int tg = y & 3, khi = y >> 2;
                sm[((lane * 7 + nt) * 32 + g * 4 + tg) * 2 + khi] = vals[y];
            }
        }
        __syncthreads();
        float4* dst = reinterpret_cast<float4*>(g_bq + (size_t)j * B_CAP_FLOATS);
        const float4* src = reinterpret_cast<const float4*>(sm);
#pragma unroll
        for (int s = 0; s < B_CAP_FLOATS / 4 / 256; ++s)
            dst[tid + s * 256] = src[tid + s * 256];
    }
}

// ---------------------------------------------------------------------------
// m16n8k8 tf32 mma
// ---------------------------------------------------------------------------
__device__ __forceinline__ void mma_tf32(float* c, const uint4& a, const uint2& b) {
    asm volatile(
        "mma.sync.aligned.m16n8k8.row.col.f32.tf32.tf32.f32 "
        "{%0,%1,%2,%3}, {%4,%5,%6,%7}, {%8,%9}, {%0,%1,%2,%3};\n"
        : "+f"(c[0]), "+f"(c[1]), "+f"(c[2]), "+f"(c[3])
        : "r"(a.x), "r"(a.y), "r"(a.z), "r"(a.w), "r"(b.x), "r"(b.y));
}

// ---------------------------------------------------------------------------
// Kernel 2: fused GEMM + Sinkhorn. 256 threads = 4 pairs x 2 warps.
// Warp w: pair p = w>>1 (ii = p>>1, jj = p&1), half h = w&1 (N-tiles h*4..).
// 3 CTAs/SM via __launch_bounds__(256,3).
// ---------------------------------------------------------------------------
__global__ __launch_bounds__(256, 3)
void wass_kernel(const int* __restrict__ img_lens,
                 const int* __restrict__ cap_lens,
                 float* __restrict__ out) {
    extern __shared__ float smem[];
    const int i0 = blockIdx.y * IP;
    const int j0 = blockIdx.x * JP;
    const int tid = threadIdx.x;
    const int lane = tid & 31;
    const int wid = tid >> 5;
    const int gid = lane >> 2;
    const int tig = lane & 3;
    const int p = wid >> 1;
    const int h = wid & 1;
    const int ii = p >> 1;
    const int jj = p & 1;
    const int nbase = h * 4;
    const int ntw = 4 - h;

    uint32_t sb;
    asm("{ .reg .u64 t; cvta.to.shared.u64 t, %1; cvt.u32.u64 %0, t; }"
        : "=r"(sb) : "l"(smem));

    // --- staging assignment (fixed): A 2 imgs x 384 quads, B 2 caps x 448 ---
    const int imA = tid >> 7, tA = tid & 127;
    const int capB = tid >> 7, tB = tid & 127;
    const float* srcA = g_aq + (size_t)(i0 + imA) * A_IMG_FLOATS + tA * 4;
    const float* srcB = g_bq + (size_t)(j0 + capB) * B_CAP_FLOATS + tB * 4;
    const uint32_t dstA = sb + imA * (A_CHUNK_FLOATS * 4) + tA * 16;
    const uint32_t dstB = sb + A_REG_FLOATS * 4 + capB * (B_CHUNK_FLOATS * 4) + tB * 16;

    float C[MT][4][4];
#pragma unroll
    for (int mt = 0; mt < MT; ++mt)
#pragma unroll
        for (int nt = 0; nt < 4; ++nt)
#pragma unroll
            for (int c = 0; c < 4; ++c) C[mt][nt][c] = 0.0f;

    // prologue: stage chunk 0 into buffer 0
    {
#pragma unroll
        for (int s = 0; s < 3; ++s)
            cp16(dstA + s * 2048, srcA + s * 512);
#pragma unroll
        for (int s = 0; s < 4; ++s)
            if (tB + s * 128 < 448) cp16(dstB + s * 2048, srcB + s * 512);
    }
    asm volatile("cp.async.commit_group;" ::: "memory");
    const float* sA = srcA + A_CHUNK_FLOATS;
    const float* sB = srcB + B_CHUNK_FLOATS;

    for (int ch = 0; ch < NCHUNK; ++ch) {
        if (ch + 1 < NCHUNK) {
            uint32_t off = ((ch + 1) & 1) * BUF_BYTES;
#pragma unroll
            for (int s = 0; s < 3; ++s)
                cp16(dstA + off + s * 2048, sA + s * 512);
#pragma unroll
            for (int s = 0; s < 4; ++s)
                if (tB + s * 128 < 448) cp16(dstB + off + s * 2048, sB + s * 512);
            asm volatile("cp.async.commit_group;" ::: "memory");
            sA += A_CHUNK_FLOATS;
            sB += B_CHUNK_FLOATS;
            asm volatile("cp.async.wait_group 1;" ::: "memory");
        } else {
            asm volatile("cp.async.wait_group 0;" ::: "memory");
        }
        __syncthreads();

        const float4* Aq = reinterpret_cast<const float4*>(
            smem + (ch & 1) * BUF_FLOATS) + ii * (A_CHUNK_FLOATS / 4);
        const float2* Bq = reinterpret_cast<const float2*>(
            smem + (ch & 1) * BUF_FLOATS + A_REG_FLOATS) + jj * (B_CHUNK_FLOATS / 2);
#pragma unroll
        for (int ks = 0; ks < NKS; ++ks) {
            uint4 a[MT];
#pragma unroll
            for (int mt = 0; mt < MT; ++mt) {
                float4 av = Aq[(ks * 3 + mt) * 32 + lane];   // one LDS.128
                a[mt].x = __float_as_uint(av.x);
                a[mt].y = __float_as_uint(av.y);
                a[mt].z = __float_as_uint(av.z);
                a[mt].w = __float_as_uint(av.w);
            }
#pragma unroll
            for (int nt = 0; nt < 4; ++nt) {
                if (nt < ntw) {
                    float2 bv = Bq[(ks * 7 + nbase + nt) * 32 + lane]; // LDS.64
                    uint2 b;
                    b.x = __float_as_uint(bv.x);
                    b.y = __float_as_uint(bv.y);
#pragma unroll
                    for (int mt = 0; mt < MT; ++mt) mma_tf32(C[mt][nt], a[mt], b);
                }
            }
        }
        __syncthreads();   // buffer (ch&1) free for restage / Sinkhorn reuse
    }

    // ---------------- Sinkhorn (2 warps = 64 threads per pair) ----------------
    const int i = i0 + ii;
    const int j = j0 + jj;
    const int Ri = img_lens[i];
    const int Wj = cap_lens[j];
    float* Kp  = smem + p * KS_STRIDE;       // [36][57]
    float* alp = smem + AL_OFF + p * RR;     // [36]
    float* bet = smem + BE_OFF + p * WW;     // [50]
    float* red = smem + RS_OFF;              // [8]
    const int t64 = h * 32 + lane;

    // K = exp((s-1)/lambda) masked; partial total sum per warp
    float tsum = 0.0f;
#pragma unroll
    for (int mt = 0; mt < MT; ++mt)
#pragma unroll
        for (int nt = 0; nt < 4; ++nt) {
            if (nt < ntw) {
#pragma unroll
                for (int c = 0; c < 4; ++c) {
                    int r = mt * 16 + gid + ((c >> 1) << 3);
                    int w = (nbase + nt) * 8 + (tig << 1) + (c & 1);
                    if (r < Ri && w < Wj) {
                        float s = C[mt][nt][c];
                        float k = __expf(ILAMB * s - ILAMB);
                        Kp[r * KW + w] = k;
                        tsum += k;
                    }
                }
            }
        }
#pragma unroll
    for (int o = 16; o > 0; o >>= 1) tsum += __shfl_xor_sync(0xffffffffu, tsum, o);
    if (lane == 0) red[wid] = tsum;
    if (t64 < WW) bet[t64] = 1.0f;
    PAIR_BAR(p);

    float alpha0 = 1.0f / (red[2 * p] + red[2 * p + 1] + EPSV);
    if (t64 < RR) alp[t64] = alpha0;
    const float rm = 1.0f / (float)Ri;
    const float cm = 1.0f / (float)Wj;
    PAIR_BAR(p);

#pragma unroll
    for (int it = 0; it < 3; ++it) {
        if (t64 < Ri) {
            float dot = 0.0f;
            for (int w = 0; w < Wj; ++w) dot += Kp[t64 * KW + w] * bet[w];
            float a = alp[t64];
            alp[t64] = a * (rm / (a * dot + EPSV));
        }
        PAIR_BAR(p);
        if (t64 < Wj) {
            float dot = 0.0f;
            for (int r = 0; r < Ri; ++r) dot += Kp[r * KW + t64] * alp[r];
            float b = bet[t64];
            bet[t64] = b * (cm / (b * dot + EPSV));
        }
        PAIR_BAR(p);
    }

    // final: sum s * K * alpha_r * beta_w over valid entries
    float acc = 0.0f;
#pragma unroll
    for (int mt = 0; mt < MT; ++mt)
#pragma unroll
        for (int nt = 0; nt < 4; ++nt) {
            if (nt < ntw) {
#pragma unroll
                for (int c = 0; c < 4; ++c) {
                    int r = mt * 16 + gid + ((c >> 1) << 3);
                    int w = (nbase + nt) * 8 + (tig << 1) + (c & 1);
                    if (r < Ri && w < Wj) {
                        float s = C[mt][nt][c];
                        float k = __expf(ILAMB * s - ILAMB);
                        acc += s * k * alp[r] * bet[w];
                    }
                }
            }
        }
#pragma unroll
    for (int o = 16; o > 0; o >>= 1) acc += __shfl_xor_sync(0xffffffffu, acc, o);
    if (lane == 0) red[wid] = acc;
    PAIR_BAR(p);
    if (h == 0 && lane == 0)
        out[i * BT + j] = red[2 * p] + red[2 * p + 1];
}

// ---------------------------------------------------------------------------
extern "C" void kernel_launch(void* const* d_in, const int* in_sizes, int n_in,
                              void* d_out, int out_size) {
    const float* imgs = (const float*)d_in[0];
    const float* caps = (const float*)d_in[1];
    const int* img_lens = (const int*)d_in[2];
    const int* cap_lens = (const int*)d_in[3];
    float* out = (float*)d_out;

    cudaFuncSetAttribute(norm_kernel,
                         cudaFuncAttributeMaxDynamicSharedMemorySize, NORM_SMEM_BYTES);
    cudaFuncSetAttribute(wass_kernel,
                         cudaFuncAttributeMaxDynamicSharedMemorySize, SMEM_BYTES);

    norm_kernel<<<BI + BT, 256, NORM_SMEM_BYTES>>>(imgs, caps);

    dim3 grid(BT / JP, BI / IP);  // (64, 64)
    wass_kernel<<<grid, 256, SMEM_BYTES>>>(img_lens, cap_lens, out);
}

// round 9
// speedup vs baseline: 1.0964x; 1.0964x over previous
#include <cuda_runtime.h>
#include <cstdint>

#define BI 128
#define BT 128
#define RR 36
#define WW 50
#define DD 256
#define ILAMB 20.0f     // 1/0.05
#define EPSV 1e-6f

#define IP 2            // imgs per block
#define JP 4            // caps per block
#define NPAIR 8         // IP*JP
#define KC 32           // K-chunk
#define NCHUNK (DD / KC)   // 8
#define MT 3            // 48 rows padded
#define NT 7            // 56 cols padded
#define NKS (KC / 8)    // 4 k-steps per chunk

// Pre-baked fragment-quad layouts in gmem (ks-major => chunk-contiguous):
// A quad (16B) at ((ks*3+mt)*32 + gid*4+tig): {A[r][k], A[r+8][k], A[r][k+4], A[r+8][k+4]}
// B pair (8B)  at ((ks*7+nt)*32 + gid*4+tig): {B[n][k], B[n][k+4]}
#define A_IMG_FLOATS (32 * MT * 128)    // 12288 per image
#define B_CAP_FLOATS (32 * NT * 64)     // 14336 per cap
#define A_CHUNK_FLOATS (NKS * MT * 128) // 1536 per image per chunk
#define B_CHUNK_FLOATS (NKS * NT * 64)  // 1792 per cap per chunk
#define A_REG_FLOATS (IP * A_CHUNK_FLOATS)  // 3072
#define B_REG_FLOATS (JP * B_CHUNK_FLOATS)  // 7168
#define BUF_FLOATS (A_REG_FLOATS + B_REG_FLOATS)  // 10240
#define BUF_BYTES (BUF_FLOATS * 4)                // 40960

// Sinkhorn scratch (reuses the two staging buffers after GEMM)
#define KW 57                           // >= WW, odd: conflict-free col walks
#define KS_STRIDE (RR * KW)             // 2052
#define KS_FLOATS (NPAIR * KS_STRIDE)   // 16416
#define AL_OFF KS_FLOATS
#define BE_OFF (KS_FLOATS + NPAIR * RR)
#define SINK_FLOATS (KS_FLOATS + NPAIR * RR + NPAIR * WW)  // 17104

#define SMEM_FLOATS (2 * BUF_FLOATS)    // 20480 > 17104
#define SMEM_BYTES (SMEM_FLOATS * 4)    // 81920

#define NORM_SMEM_BYTES (B_CAP_FLOATS * 4)   // 57344 (max of A/B block)

__device__ float g_aq[BI * A_IMG_FLOATS];
__device__ float g_bq[BT * B_CAP_FLOATS];

__device__ __forceinline__ unsigned f2tf32(float x) {
    unsigned r;
    asm("cvt.rna.tf32.f32 %0, %1;" : "=r"(r) : "f"(x));
    return r;
}

__device__ __forceinline__ void cp16(uint32_t dst, const float* src) {
    asm volatile("cp.async.cg.shared.global [%0], [%1], 16;\n"
                 :: "r"(dst), "l"(src));
}

// ---------------------------------------------------------------------------
// Kernel 1: L2-normalize, round to tf32, build fragment-quad layout in smem,
// dump coalesced. One block per image (b < BI) or cap (b >= BI).
// ---------------------------------------------------------------------------
__global__ __launch_bounds__(256)
void norm_kernel(const float* __restrict__ imgs,
                 const float* __restrict__ caps) {
    extern __shared__ float sm[];
    const int b = blockIdx.x;
    const int tid = threadIdx.x;
    const int lane = tid & 31;   // = ks block (k = 8*lane .. 8*lane+7)
    const int wrp = tid >> 5;

    if (b < BI) {
        // ---- image b : 48 padded rows ----
        for (int r = wrp; r < 48; r += 8) {
            float vals[8];
            if (r < RR) {
                const float4* s4 = reinterpret_cast<const float4*>(
                    imgs + ((size_t)b * RR + r) * DD);
                float4 v0 = s4[2 * lane], v1 = s4[2 * lane + 1];
                float ss = v0.x * v0.x + v0.y * v0.y + v0.z * v0.z + v0.w * v0.w
                         + v1.x * v1.x + v1.y * v1.y + v1.z * v1.z + v1.w * v1.w;
#pragma unroll
                for (int o = 16; o > 0; o >>= 1)
                    ss += __shfl_xor_sync(0xffffffffu, ss, o);
                float inv = 1.0f / fmaxf(sqrtf(ss), 1e-8f);
                vals[0] = __uint_as_float(f2tf32(v0.x * inv));
                vals[1] = __uint_as_float(f2tf32(v0.y * inv));
                vals[2] = __uint_as_float(f2tf32(v0.z * inv));
                vals[3] = __uint_as_float(f2tf32(v0.w * inv));
                vals[4] = __uint_as_float(f2tf32(v1.x * inv));
                vals[5] = __uint_as_float(f2tf32(v1.y * inv));
                vals[6] = __uint_as_float(f2tf32(v1.z * inv));
                vals[7] = __uint_as_float(f2tf32(v1.w * inv));
            } else {
#pragma unroll
                for (int y = 0; y < 8; ++y) vals[y] = 0.0f;
            }
            int mt = r >> 4, x = r & 15, g = x & 7, hi = x >> 3;
#pragma unroll
            for (int y = 0; y < 8; ++y) {
                int tg = y & 3, khi = y >> 2;
                sm[((lane * 3 + mt) * 32 + g * 4 + tg) * 4 + khi * 2 + hi] = vals[y];
            }
        }
        __syncthreads();
        float4* dst = reinterpret_cast<float4*>(g_aq + (size_t)b * A_IMG_FLOATS);
        const float4* src = reinterpret_cast<const float4*>(sm);
#pragma unroll
        for (int s = 0; s < A_IMG_FLOATS / 4 / 256; ++s)
            dst[tid + s * 256] = src[tid + s * 256];
    } else {
        // ---- cap j : 56 padded rows ----
        const int j = b - BI;
        for (int w = wrp; w < 56; w += 8) {
            float vals[8];
            if (w < WW) {
                const float4* s4 = reinterpret_cast<const float4*>(
                    caps + ((size_t)j * WW + w) * DD);
                float4 v0 = s4[2 * lane], v1 = s4[2 * lane + 1];
                float ss = v0.x * v0.x + v0.y * v0.y + v0.z * v0.z + v0.w * v0.w
                         + v1.x * v1.x + v1.y * v1.y + v1.z * v1.z + v1.w * v1.w;
#pragma unroll
                for (int o = 16; o > 0; o >>= 1)
                    ss += __shfl_xor_sync(0xffffffffu, ss, o);
                float inv = 1.0f / fmaxf(sqrtf(ss), 1e-8f);
                vals[0] = __uint_as_float(f2tf32(v0.x * inv));
                vals[1] = __uint_as_float(f2tf32(v0.y * inv));
                vals[2] = __uint_as_float(f2tf32(v0.z * inv));
                vals[3] = __uint_as_float(f2tf32(v0.w * inv));
                vals[4] = __uint_as_float(f2tf32(v1.x * inv));
                vals[5] = __uint_as_float(f2tf32(v1.y * inv));
                vals[6] = __uint_as_float(f2tf32(v1.z * inv));
                vals[7] = __uint_as_float(f2tf32(v1.w * inv));
            } else {
#pragma unroll
                for (int y = 0; y < 8; ++y) vals[y] = 0.0f;
            }
            int nt = w >> 3, g = w & 7;
#pragma unroll
            for (int y = 0; y < 8; ++y) {
                int tg = y & 3, khi = y >> 2;
                sm[((lane * 7 + nt) * 32 + g * 4 + tg) * 2 + khi] = vals[y];
            }
        }
        __syncthreads();
        float4* dst = reinterpret_cast<float4*>(g_bq + (size_t)j * B_CAP_FLOATS);
        const float4* src = reinterpret_cast<const float4*>(sm);
#pragma unroll
        for (int s = 0; s < B_CAP_FLOATS / 4 / 256; ++s)
            dst[tid + s * 256] = src[tid + s * 256];
    }
}

// ---------------------------------------------------------------------------
// m16n8k8 tf32 mma
// ---------------------------------------------------------------------------
__device__ __forceinline__ void mma_tf32(float* c, const uint4& a, const uint2& b) {
    asm volatile(
        "mma.sync.aligned.m16n8k8.row.col.f32.tf32.tf32.f32 "
        "{%0,%1,%2,%3}, {%4,%5,%6,%7}, {%8,%9}, {%0,%1,%2,%3};\n"
        : "+f"(c[0]), "+f"(c[1]), "+f"(c[2]), "+f"(c[3])
        : "r"(a.x), "r"(a.y), "r"(a.z), "r"(a.w), "r"(b.x), "r"(b.y));
}

// Stage one chunk: pure bulk copy, constant strides, zero index math.
__device__ __forceinline__ void stage(const float* srcA, uint32_t dstA,
                                      const float* srcB, uint32_t dstB) {
#pragma unroll
    for (int s = 0; s < 3; ++s)
        cp16(dstA + s * 2048, srcA + s * 512);   // 128 quads per step
#pragma unroll
    for (int s = 0; s < 7; ++s)
        cp16(dstB + s * 1024, srcB + s * 256);   // 64 quads per step
}

// ---------------------------------------------------------------------------
// Kernel 2: fused GEMM (tf32 mma.sync, cp.async double-buffered) + Sinkhorn.
// Block = IP imgs x JP caps; warp w owns pair (ii = w>>2, jj = w&3).
// ---------------------------------------------------------------------------
__global__ __launch_bounds__(256, 2)
void wass_kernel(const int* __restrict__ img_lens,
                 const int* __restrict__ cap_lens,
                 float* __restrict__ out) {
    extern __shared__ float smem[];
    const int i0 = blockIdx.y * IP;
    const int j0 = blockIdx.x * JP;
    const int tid = threadIdx.x;
    const int lane = tid & 31;
    const int wid = tid >> 5;
    const int gid = lane >> 2;
    const int tig = lane & 3;
    const int ii = wid >> 2;
    const int jj = wid & 3;

    uint32_t sb;
    asm("{ .reg .u64 t; cvta.to.shared.u64 t, %1; cvt.u32.u64 %0, t; }"
        : "=r"(sb) : "l"(smem));

    // --- per-thread staging assignment (fixed for all chunks) ---
    const int imA = tid >> 7, tA = tid & 127;       // A: img = tid/128, 3 quads @ +128
    const int capB = tid >> 6, tB = tid & 63;       // B: cap = tid/64,  7 quads @ +64
    const float* srcA = g_aq + (size_t)(i0 + imA) * A_IMG_FLOATS + tA * 4;
    const float* srcB = g_bq + (size_t)(j0 + capB) * B_CAP_FLOATS + tB * 4;
    const uint32_t dstA = sb + imA * (A_CHUNK_FLOATS * 4) + tA * 16;
    const uint32_t dstB = sb + A_REG_FLOATS * 4 + capB * (B_CHUNK_FLOATS * 4) + tB * 16;

    float C[MT][NT][4];
#pragma unroll
    for (int mt = 0; mt < MT; ++mt)
#pragma unroll
        for (int nt = 0; nt < NT; ++nt)
#pragma unroll
            for (int c = 0; c < 4; ++c) C[mt][nt][c] = 0.0f;

    // prologue: stage chunk 0 into buffer 0
    stage(srcA, dstA, srcB, dstB);
    asm volatile("cp.async.commit_group;" ::: "memory");
    const float* sA = srcA + A_CHUNK_FLOATS;
    const float* sB = srcB + B_CHUNK_FLOATS;

    for (int ch = 0; ch < NCHUNK; ++ch) {
        if (ch + 1 < NCHUNK) {
            uint32_t off = ((ch + 1) & 1) * BUF_BYTES;
            stage(sA, dstA + off, sB, dstB + off);
            asm volatile("cp.async.commit_group;" ::: "memory");
            sA += A_CHUNK_FLOATS;
            sB += B_CHUNK_FLOATS;
            asm volatile("cp.async.wait_group 1;" ::: "memory");
        } else {
            asm volatile("cp.async.wait_group 0;" ::: "memory");
        }
        __syncthreads();

        const float4* Aq = reinterpret_cast<const float4*>(
            smem + (ch & 1) * BUF_FLOATS) + ii * (A_CHUNK_FLOATS / 4);
        const float2* Bq = reinterpret_cast<const float2*>(
            smem + (ch & 1) * BUF_FLOATS + A_REG_FLOATS) + jj * (B_CHUNK_FLOATS / 2);
#pragma unroll
        for (int ks = 0; ks < NKS; ++ks) {
            uint4 a[MT];
#pragma unroll
            for (int mt = 0; mt < MT; ++mt) {
                float4 av = Aq[(ks * 3 + mt) * 32 + lane];   // one LDS.128
                a[mt].x = __float_as_uint(av.x);
                a[mt].y = __float_as_uint(av.y);
                a[mt].z = __float_as_uint(av.z);
                a[mt].w = __float_as_uint(av.w);
            }
#pragma unroll
            for (int nt = 0; nt < NT; ++nt) {
                float2 bv = Bq[(ks * 7 + nt) * 32 + lane];   // one LDS.64
                uint2 b;
                b.x = __float_as_uint(bv.x);
                b.y = __float_as_uint(bv.y);
#pragma unroll
                for (int mt = 0; mt < MT; ++mt) mma_tf32(C[mt][nt], a[mt], b);
            }
        }
        __syncthreads();   // buffer (ch&1) free for restage / Sinkhorn reuse
    }

    // ---------------- Sinkhorn (warp-private per pair) ----------------
    const int i = i0 + ii;
    const int j = j0 + jj;
    const int Ri = img_lens[i];
    const int Wj = cap_lens[j];
    float* Kp = smem + wid * KS_STRIDE;        // [36][57]
    float* alp = smem + AL_OFF + wid * RR;     // [36]
    float* bet = smem + BE_OFF + wid * WW;     // [50]

    // K = exp((s-1)/lambda) masked; accumulate total sum
    float tsum = 0.0f;
#pragma unroll
    for (int mt = 0; mt < MT; ++mt)
#pragma unroll
        for (int nt = 0; nt < NT; ++nt)
#pragma unroll
            for (int c = 0; c < 4; ++c) {
                int r = mt * 16 + gid + ((c >> 1) << 3);
                int w = nt * 8 + (tig << 1) + (c & 1);
                if (r < Ri && w < Wj) {
                    float s = C[mt][nt][c];
                    float k = __expf(ILAMB * s - ILAMB);
                    Kp[r * KW + w] = k;
                    tsum += k;
                }
            }
#pragma unroll
    for (int o = 16; o > 0; o >>= 1) tsum += __shfl_xor_sync(0xffffffffu, tsum, o);
    float alpha0 = 1.0f / (tsum + EPSV);

    for (int r = lane; r < Ri; r += 32) alp[r] = alpha0;
    for (int w = lane; w < Wj; w += 32) bet[w] = 1.0f;
    const float rm = 1.0f / (float)Ri;
    const float cm = 1.0f / (float)Wj;
    __syncwarp();

#pragma unroll
    for (int it = 0; it < 3; ++it) {
        for (int r = lane; r < Ri; r += 32) {
            float dot = 0.0f;
            for (int w = 0; w < Wj; ++w) dot += Kp[r * KW + w] * bet[w];
            float a = alp[r];
            alp[r] = a * (rm / (a * dot + EPSV));
        }
        __syncwarp();
        for (int w = lane; w < Wj; w += 32) {
            float dot = 0.0f;
            for (int r = 0; r < Ri; ++r) dot += Kp[r * KW + w] * alp[r];
            float b = bet[w];
            bet[w] = b * (cm / (b * dot + EPSV));
        }
        __syncwarp();
    }

    // final: sum s * K * alpha_r * beta_w over valid entries
    float acc = 0.0f;
#pragma unroll
    for (int mt = 0; mt < MT; ++mt)
#pragma unroll
        for (int nt = 0; nt < NT; ++nt)
#pragma unroll
            for (int c = 0; c < 4; ++c) {
                int r = mt * 16 + gid + ((c >> 1) << 3);
                int w = nt * 8 + (tig << 1) + (c & 1);
                if (r < Ri && w < Wj) {
                    float s = C[mt][nt][c];
                    float k = __expf(ILAMB * s - ILAMB);
                    acc += s * k * alp[r] * bet[w];
                }
            }
#pragma unroll
    for (int o = 16; o > 0; o >>= 1) acc += __shfl_xor_sync(0xffffffffu, acc, o);
    if (lane == 0) out[i * BT + j] = acc;
}

// ---------------------------------------------------------------------------
extern "C" void kernel_launch(void* const* d_in, const int* in_sizes, int n_in,
                              void* d_out, int out_size) {
    const float* imgs = (const float*)d_in[0];
    const float* caps = (const float*)d_in[1];
    const int* img_lens = (const int*)d_in[2];
    const int* cap_lens = (const int*)d_in[3];
    float* out = (float*)d_out;

    cudaFuncSetAttribute(norm_kernel,
                         cudaFuncAttributeMaxDynamicSharedMemorySize, NORM_SMEM_BYTES);
    cudaFuncSetAttribute(wass_kernel,
                         cudaFuncAttributeMaxDynamicSharedMemorySize, SMEM_BYTES);

    norm_kernel<<<BI + BT, 256, NORM_SMEM_BYTES>>>(imgs, caps);

    dim3 grid(BT / JP, BI / IP);  // (32, 64)
    wass_kernel<<<grid, 256, SMEM_BYTES>>>(img_lens, cap_lens, out);
}

// round 10
// speedup vs baseline: 1.4118x; 1.2877x over previous
#include <cuda_runtime.h>
#include <cuda_fp16.h>
#include <cstdint>

#define BI 128
#define BT 128
#define RR 36
#define WW 50
#define DD 256
#define ILAMB 20.0f     // 1/0.05
#define EPSV 1e-6f

#define IP 2            // imgs per block
#define JP 4            // caps per block
#define NPAIR 8         // IP*JP
#define KC 64           // K-chunk (4 x k16 mma steps)
#define NCHUNK (DD / KC)   // 4
#define MT 3            // 48 rows padded
#define NT 7            // 56 cols padded
#define NKS (KC / 16)   // 4 k-steps per chunk
#define NKS_TOT (DD / 16)  // 16 global k-steps

// Pre-baked fp16 fragment layouts in gmem (u32 = f16x2), ks-major:
// A quad (4xu32/lane) at ((ksg*3+mt)*32 + lane): {a0,a1,a2,a3} of m16n8k16
// B pair (2xu32/lane) at ((ksg*7+nt)*32 + lane): {b0,b1}
#define A_IMG_U32 (NKS_TOT * MT * 128)   // 6144 per image
#define B_CAP_U32 (NKS_TOT * NT * 64)    // 7168 per cap
#define A_CHUNK_U32 (NKS * MT * 128)     // 1536 per image per chunk
#define B_CHUNK_U32 (NKS * NT * 64)      // 1792 per cap per chunk
#define A_REG_U32 (IP * A_CHUNK_U32)     // 3072
#define B_REG_U32 (JP * B_CHUNK_U32)     // 7168
#define BUF_U32 (A_REG_U32 + B_REG_U32)  // 10240
#define BUF_BYTES (BUF_U32 * 4)          // 40960

// Sinkhorn scratch (fp32; reuses the two staging buffers after GEMM)
#define KW 57                           // >= WW, odd: conflict-free col walks
#define KS_STRIDE (RR * KW)             // 2052
#define KS_FLOATS (NPAIR * KS_STRIDE)   // 16416
#define AL_OFF KS_FLOATS
#define BE_OFF (KS_FLOATS + NPAIR * RR)

#define SMEM_U32 (2 * BUF_U32)          // 20480 (> 17104 Sinkhorn floats)
#define SMEM_BYTES (SMEM_U32 * 4)       // 81920

#define NORM_SMEM_BYTES (B_CAP_U32 * 4) // 28672 (max of A/B block)

__device__ uint32_t g_aq[BI * A_IMG_U32];
__device__ uint32_t g_bq[BT * B_CAP_U32];

__device__ __forceinline__ uint32_t pack_h2(float lo, float hi) {
    uint32_t r;
    asm("cvt.rn.f16x2.f32 %0, %1, %2;" : "=r"(r) : "f"(hi), "f"(lo));
    return r;
}

__device__ __forceinline__ void cp16(uint32_t dst, const void* src) {
    asm volatile("cp.async.cg.shared.global [%0], [%1], 16;\n"
                 :: "r"(dst), "l"(src));
}

// ---------------------------------------------------------------------------
// Kernel 1: L2-normalize, convert to fp16 pairs, build fragment layout in
// smem, dump coalesced. One block per image (b < BI) or cap (b >= BI).
// Lane L owns k-octet 8L..8L+7: ksg = L>>1, sel = L&1 (k-offset 8*sel).
// ---------------------------------------------------------------------------
__global__ __launch_bounds__(256)
void norm_kernel(const float* __restrict__ imgs,
                 const float* __restrict__ caps) {
    extern __shared__ uint32_t sm[];
    const int b = blockIdx.x;
    const int tid = threadIdx.x;
    const int lane = tid & 31;
    const int wrp = tid >> 5;
    const int ksg = lane >> 1;
    const int sel = lane & 1;

    if (b < BI) {
        for (int r = wrp; r < 48; r += 8) {
            float v[8];
            if (r < RR) {
                const float4* s4 = reinterpret_cast<const float4*>(
                    imgs + ((size_t)b * RR + r) * DD);
                float4 v0 = s4[2 * lane], v1 = s4[2 * lane + 1];
                float ss = v0.x * v0.x + v0.y * v0.y + v0.z * v0.z + v0.w * v0.w
                         + v1.x * v1.x + v1.y * v1.y + v1.z * v1.z + v1.w * v1.w;
#pragma unroll
                for (int o = 16; o > 0; o >>= 1)
                    ss += __shfl_xor_sync(0xffffffffu, ss, o);
                float inv = 1.0f / fmaxf(sqrtf(ss), 1e-8f);
                v[0] = v0.x * inv; v[1] = v0.y * inv;
                v[2] = v0.z * inv; v[3] = v0.w * inv;
                v[4] = v1.x * inv; v[5] = v1.y * inv;
                v[6] = v1.z * inv; v[7] = v1.w * inv;
            } else {
#pragma unroll
                for (int y = 0; y < 8; ++y) v[y] = 0.0f;
            }
            int mt = r >> 4, x = r & 15, g = x & 7, hi = x >> 3;
#pragma unroll
            for (int t = 0; t < 4; ++t) {
                sm[((ksg * 3 + mt) * 32 + g * 4 + t) * 4 + sel * 2 + hi] =
                    pack_h2(v[2 * t], v[2 * t + 1]);
            }
        }
        __syncthreads();
        uint4* dst = reinterpret_cast<uint4*>(g_aq + (size_t)b * A_IMG_U32);
        const uint4* src = reinterpret_cast<const uint4*>(sm);
#pragma unroll
        for (int s = 0; s < A_IMG_U32 / 4 / 256; ++s)
            dst[tid + s * 256] = src[tid + s * 256];
    } else {
        const int j = b - BI;
        for (int w = wrp; w < 56; w += 8) {
            float v[8];
            if (w < WW) {
                const float4* s4 = reinterpret_cast<const float4*>(
                    caps + ((size_t)j * WW + w) * DD);
                float4 v0 = s4[2 * lane], v1 = s4[2 * lane + 1];
                float ss = v0.x * v0.x + v0.y * v0.y + v0.z * v0.z + v0.w * v0.w
                         + v1.x * v1.x + v1.y * v1.y + v1.z * v1.z + v1.w * v1.w;
#pragma unroll
                for (int o = 16; o > 0; o >>= 1)
                    ss += __shfl_xor_sync(0xffffffffu, ss, o);
                float inv = 1.0f / fmaxf(sqrtf(ss), 1e-8f);
                v[0] = v0.x * inv; v[1] = v0.y * inv;
                v[2] = v0.z * inv; v[3] = v0.w * inv;
                v[4] = v1.x * inv; v[5] = v1.y * inv;
                v[6] = v1.z * inv; v[7] = v1.w * inv;
            } else {
#pragma unroll
                for (int y = 0; y < 8; ++y) v[y] = 0.0f;
            }
            int nt = w >> 3, g = w & 7;
#pragma unroll
            for (int t = 0; t < 4; ++t) {
                sm[((ksg * 7 + nt) * 32 + g * 4 + t) * 2 + sel] =
                    pack_h2(v[2 * t], v[2 * t + 1]);
            }
        }
        __syncthreads();
        uint4* dst = reinterpret_cast<uint4*>(g_bq + (size_t)j * B_CAP_U32);
        const uint4* src = reinterpret_cast<const uint4*>(sm);
#pragma unroll
        for (int s = 0; s < B_CAP_U32 / 4 / 256; ++s)
            dst[tid + s * 256] = src[tid + s * 256];
    }
}

// ---------------------------------------------------------------------------
// m16n8k16 fp16 mma, fp32 accumulate
// ---------------------------------------------------------------------------
__device__ __forceinline__ void mma_f16(float* c, const uint4& a, const uint2& b) {
    asm volatile(
        "mma.sync.aligned.m16n8k16.row.col.f32.f16.f16.f32 "
        "{%0,%1,%2,%3}, {%4,%5,%6,%7}, {%8,%9}, {%0,%1,%2,%3};\n"
        : "+f"(c[0]), "+f"(c[1]), "+f"(c[2]), "+f"(c[3])
        : "r"(a.x), "r"(a.y), "r"(a.z), "r"(a.w), "r"(b.x), "r"(b.y));
}

// Stage one chunk: pure bulk copy, constant strides, zero index math.
// A: 2 imgs x 384 quads (threads 0-127 / 128-255, 3 each).
// B: 4 caps x 448 quads (64 threads per cap, 7 each).
__device__ __forceinline__ void stage(const uint32_t* srcA, uint32_t dstA,
                                      const uint32_t* srcB, uint32_t dstB) {
#pragma unroll
    for (int s = 0; s < 3; ++s)
        cp16(dstA + s * 2048, srcA + s * 512);
#pragma unroll
    for (int s = 0; s < 7; ++s)
        cp16(dstB + s * 1024, srcB + s * 256);
}

// ---------------------------------------------------------------------------
// Kernel 2: fused GEMM (fp16 mma.sync, cp.async double-buffered) + Sinkhorn.
// Block = IP imgs x JP caps; warp w owns pair (ii = w>>2, jj = w&3).
// ---------------------------------------------------------------------------
__global__ __launch_bounds__(256, 2)
void wass_kernel(const int* __restrict__ img_lens,
                 const int* __restrict__ cap_lens,
                 float* __restrict__ out) {
    extern __shared__ float smem[];
    uint32_t* sm32 = reinterpret_cast<uint32_t*>(smem);
    const int i0 = blockIdx.y * IP;
    const int j0 = blockIdx.x * JP;
    const int tid = threadIdx.x;
    const int lane = tid & 31;
    const int wid = tid >> 5;
    const int gid = lane >> 2;
    const int tig = lane & 3;
    const int ii = wid >> 2;
    const int jj = wid & 3;

    uint32_t sb;
    asm("{ .reg .u64 t; cvta.to.shared.u64 t, %1; cvt.u32.u64 %0, t; }"
        : "=r"(sb) : "l"(smem));

    // --- per-thread staging assignment (fixed for all chunks) ---
    const int imA = tid >> 7, tA = tid & 127;
    const int capB = tid >> 6, tB = tid & 63;
    const uint32_t* srcA = g_aq + (size_t)(i0 + imA) * A_IMG_U32 + tA * 4;
    const uint32_t* srcB = g_bq + (size_t)(j0 + capB) * B_CAP_U32 + tB * 4;
    const uint32_t dstA = sb + imA * (A_CHUNK_U32 * 4) + tA * 16;
    const uint32_t dstB = sb + A_REG_U32 * 4 + capB * (B_CHUNK_U32 * 4) + tB * 16;

    float C[MT][NT][4];
#pragma unroll
    for (int mt = 0; mt < MT; ++mt)
#pragma unroll
        for (int nt = 0; nt < NT; ++nt)
#pragma unroll
            for (int c = 0; c < 4; ++c) C[mt][nt][c] = 0.0f;

    // prologue: stage chunk 0 into buffer 0
    stage(srcA, dstA, srcB, dstB);
    asm volatile("cp.async.commit_group;" ::: "memory");
    const uint32_t* sA = srcA + A_CHUNK_U32;
    const uint32_t* sB = srcB + B_CHUNK_U32;

    for (int ch = 0; ch < NCHUNK; ++ch) {
        if (ch + 1 < NCHUNK) {
            uint32_t off = ((ch + 1) & 1) * BUF_BYTES;
            stage(sA, dstA + off, sB, dstB + off);
            asm volatile("cp.async.commit_group;" ::: "memory");
            sA += A_CHUNK_U32;
            sB += B_CHUNK_U32;
            asm volatile("cp.async.wait_group 1;" ::: "memory");
        } else {
            asm volatile("cp.async.wait_group 0;" ::: "memory");
        }
        __syncthreads();

        const uint4* Aq = reinterpret_cast<const uint4*>(
            sm32 + (ch & 1) * BUF_U32) + ii * (A_CHUNK_U32 / 4);
        const uint2* Bq = reinterpret_cast<const uint2*>(
            sm32 + (ch & 1) * BUF_U32 + A_REG_U32) + jj * (B_CHUNK_U32 / 2);
#pragma unroll
        for (int ks = 0; ks < NKS; ++ks) {
            uint4 a[MT];
#pragma unroll
            for (int mt = 0; mt < MT; ++mt)
                a[mt] = Aq[(ks * 3 + mt) * 32 + lane];       // one LDS.128
#pragma unroll
            for (int nt = 0; nt < NT; ++nt) {
                uint2 b = Bq[(ks * 7 + nt) * 32 + lane];     // one LDS.64
#pragma unroll
                for (int mt = 0; mt < MT; ++mt) mma_f16(C[mt][nt], a[mt], b);
            }
        }
        __syncthreads();   // buffer (ch&1) free for restage / Sinkhorn reuse
    }

    // ---------------- Sinkhorn (warp-private per pair) ----------------
    const int i = i0 + ii;
    const int j = j0 + jj;
    const int Ri = img_lens[i];
    const int Wj = cap_lens[j];
    float* Kp = smem + wid * KS_STRIDE;        // [36][57]
    float* alp = smem + AL_OFF + wid * RR;     // [36]
    float* bet = smem + BE_OFF + wid * WW;     // [50]

    // K = exp((s-1)/lambda) masked; accumulate total sum
    float tsum = 0.0f;
#pragma unroll
    for (int mt = 0; mt < MT; ++mt)
#pragma unroll
        for (int nt = 0; nt < NT; ++nt)
#pragma unroll
            for (int c = 0; c < 4; ++c) {
                int r = mt * 16 + gid + ((c >> 1) << 3);
                int w = nt * 8 + (tig << 1) + (c & 1);
                if (r < Ri && w < Wj) {
                    float s = C[mt][nt][c];
                    float k = __expf(ILAMB * s - ILAMB);
                    Kp[r * KW + w] = k;
                    tsum += k;
                }
            }
#pragma unroll
    for (int o = 16; o > 0; o >>= 1) tsum += __shfl_xor_sync(0xffffffffu, tsum, o);
    float alpha0 = 1.0f / (tsum + EPSV);

    for (int r = lane; r < Ri; r += 32) alp[r] = alpha0;
    for (int w = lane; w < Wj; w += 32) bet[w] = 1.0f;
    const float rm = 1.0f / (float)Ri;
    const float cm = 1.0f / (float)Wj;
    __syncwarp();

#pragma unroll
    for (int it = 0; it < 3; ++it) {
        for (int r = lane; r < Ri; r += 32) {
            float dot = 0.0f;
            for (int w = 0; w < Wj; ++w) dot += Kp[r * KW + w] * bet[w];
            float a = alp[r];
            alp[r] = a * (rm / (a * dot + EPSV));
        }
        __syncwarp();
        for (int w = lane; w < Wj; w += 32) {
            float dot = 0.0f;
            for (int r = 0; r < Ri; ++r) dot += Kp[r * KW + w] * alp[r];
            float b = bet[w];
            bet[w] = b * (cm / (b * dot + EPSV));
        }
        __syncwarp();
    }

    // final: sum s * K * alpha_r * beta_w over valid entries
    float acc = 0.0f;
#pragma unroll
    for (int mt = 0; mt < MT; ++mt)
#pragma unroll
        for (int nt = 0; nt < NT; ++nt)
#pragma unroll
            for (int c = 0; c < 4; ++c) {
                int r = mt * 16 + gid + ((c >> 1) << 3);
                int w = nt * 8 + (tig << 1) + (c & 1);
                if (r < Ri && w < Wj) {
                    float s = C[mt][nt][c];
                    float k = __expf(ILAMB * s - ILAMB);
                    acc += s * k * alp[r] * bet[w];
                }
            }
#pragma unroll
    for (int o = 16; o > 0; o >>= 1) acc += __shfl_xor_sync(0xffffffffu, acc, o);
    if (lane == 0) out[i * BT + j] = acc;
}

// ---------------------------------------------------------------------------
extern "C" void kernel_launch(void* const* d_in, const int* in_sizes, int n_in,
                              void* d_out, int out_size) {
    const float* imgs = (const float*)d_in[0];
    const float* caps = (const float*)d_in[1];
    const int* img_lens = (const int*)d_in[2];
    const int* cap_lens = (const int*)d_in[3];
    float* out = (float*)d_out;

    cudaFuncSetAttribute(norm_kernel,
                         cudaFuncAttributeMaxDynamicSharedMemorySize, NORM_SMEM_BYTES);
    cudaFuncSetAttribute(wass_kernel,
                         cudaFuncAttributeMaxDynamicSharedMemorySize, SMEM_BYTES);

    norm_kernel<<<BI + BT, 256, NORM_SMEM_BYTES>>>(imgs, caps);

    dim3 grid(BT / JP, BI / IP);  // (32, 64)
    wass_kernel<<<grid, 256, SMEM_BYTES>>>(img_lens, cap_lens, out);
}

// round 11
// speedup vs baseline: 1.5387x; 1.0899x over previous
#include <cuda_runtime.h>
#include <cuda_fp16.h>
#include <cstdint>

#define BI 128
#define BT 128
#define RR 36
#define WW 50
#define DD 256
#define ILAMB 20.0f     // 1/0.05
#define EPSV 1e-6f

#define IP 2            // imgs per block
#define JP 4            // caps per block
#define NPAIR 8         // IP*JP
#define KC 64           // K-chunk (4 x k16 mma steps)
#define NCHUNK (DD / KC)   // 4
#define MT 3            // 48 rows padded
#define NT 7            // 56 cols padded
#define NKS (KC / 16)   // 4 k-steps per chunk
#define NKS_TOT (DD / 16)  // 16 global k-steps

// Pre-baked fp16 fragment layouts in gmem (u32 = f16x2), ks-major:
// A quad (4xu32/lane) at ((ksg*3+mt)*32 + lane): {a0,a1,a2,a3} of m16n8k16
// B pair (2xu32/lane) at ((ksg*7+nt)*32 + lane): {b0,b1}
#define A_IMG_U32 (NKS_TOT * MT * 128)   // 6144 per image
#define B_CAP_U32 (NKS_TOT * NT * 64)    // 7168 per cap
#define A_CHUNK_U32 (NKS * MT * 128)     // 1536 per image per chunk
#define B_CHUNK_U32 (NKS * NT * 64)      // 1792 per cap per chunk
#define A_REG_U32 (IP * A_CHUNK_U32)     // 3072
#define B_REG_U32 (JP * B_CHUNK_U32)     // 7168
#define BUF_U32 (A_REG_U32 + B_REG_U32)  // 10240
#define BUF_BYTES (BUF_U32 * 4)          // 40960

// Sinkhorn scratch (fp32; reuses the two staging buffers after GEMM)
#define KW 57                           // >= WW, odd: conflict-free col walks
#define KS_STRIDE (RR * KW)             // 2052
#define KS_FLOATS (NPAIR * KS_STRIDE)   // 16416
#define AL_OFF KS_FLOATS
#define BE_OFF (KS_FLOATS + NPAIR * RR)

#define SMEM_U32 (2 * BUF_U32)          // 20480 (> 17104 Sinkhorn floats)
#define SMEM_BYTES (SMEM_U32 * 4)       // 81920

#define NORM_SMEM_BYTES (B_CAP_U32 * 4) // 28672 (max of A/B block)

__device__ uint32_t g_aq[BI * A_IMG_U32];
__device__ uint32_t g_bq[BT * B_CAP_U32];

__device__ __forceinline__ uint32_t pack_h2(float lo, float hi) {
    uint32_t r;
    asm("cvt.rn.f16x2.f32 %0, %1, %2;" : "=r"(r) : "f"(hi), "f"(lo));
    return r;
}

__device__ __forceinline__ void cp16(uint32_t dst, const void* src) {
    asm volatile("cp.async.cg.shared.global [%0], [%1], 16;\n"
                 :: "r"(dst), "l"(src));
}

// ---------------------------------------------------------------------------
// Kernel 1: L2-normalize, convert to fp16 pairs, build fragment layout in
// smem, dump coalesced. One block per image (b < BI) or cap (b >= BI).
// Lane L owns k-octet 8L..8L+7: ksg = L>>1, sel = L&1 (k-offset 8*sel).
// ---------------------------------------------------------------------------
__global__ __launch_bounds__(256)
void norm_kernel(const float* __restrict__ imgs,
                 const float* __restrict__ caps) {
    extern __shared__ uint32_t sm[];
    const int b = blockIdx.x;
    const int tid = threadIdx.x;
    const int lane = tid & 31;
    const int wrp = tid >> 5;
    const int ksg = lane >> 1;
    const int sel = lane & 1;

    if (b < BI) {
        for (int r = wrp; r < 48; r += 8) {
            float v[8];
            if (r < RR) {
                const float4* s4 = reinterpret_cast<const float4*>(
                    imgs + ((size_t)b * RR + r) * DD);
                float4 v0 = s4[2 * lane], v1 = s4[2 * lane + 1];
                float ss = v0.x * v0.x + v0.y * v0.y + v0.z * v0.z + v0.w * v0.w
                         + v1.x * v1.x + v1.y * v1.y + v1.z * v1.z + v1.w * v1.w;
#pragma unroll
                for (int o = 16; o > 0; o >>= 1)
                    ss += __shfl_xor_sync(0xffffffffu, ss, o);
                float inv = 1.0f / fmaxf(sqrtf(ss), 1e-8f);
                v[0] = v0.x * inv; v[1] = v0.y * inv;
                v[2] = v0.z * inv; v[3] = v0.w * inv;
                v[4] = v1.x * inv; v[5] = v1.y * inv;
                v[6] = v1.z * inv; v[7] = v1.w * inv;
            } else {
#pragma unroll
                for (int y = 0; y < 8; ++y) v[y] = 0.0f;
            }
            int mt = r >> 4, x = r & 15, g = x & 7, hi = x >> 3;
#pragma unroll
            for (int t = 0; t < 4; ++t) {
                sm[((ksg * 3 + mt) * 32 + g * 4 + t) * 4 + sel * 2 + hi] =
                    pack_h2(v[2 * t], v[2 * t + 1]);
            }
        }
        __syncthreads();
        uint4* dst = reinterpret_cast<uint4*>(g_aq + (size_t)b * A_IMG_U32);
        const uint4* src = reinterpret_cast<const uint4*>(sm);
#pragma unroll
        for (int s = 0; s < A_IMG_U32 / 4 / 256; ++s)
            dst[tid + s * 256] = src[tid + s * 256];
    } else {
        const int j = b - BI;
        for (int w = wrp; w < 56; w += 8) {
            float v[8];
            if (w < WW) {
                const float4* s4 = reinterpret_cast<const float4*>(
                    caps + ((size_t)j * WW + w) * DD);
                float4 v0 = s4[2 * lane], v1 = s4[2 * lane + 1];
                float ss = v0.x * v0.x + v0.y * v0.y + v0.z * v0.z + v0.w * v0.w
                         + v1.x * v1.x + v1.y * v1.y + v1.z * v1.z + v1.w * v1.w;
#pragma unroll
                for (int o = 16; o > 0; o >>= 1)
                    ss += __shfl_xor_sync(0xffffffffu, ss, o);
                float inv = 1.0f / fmaxf(sqrtf(ss), 1e-8f);
                v[0] = v0.x * inv; v[1] = v0.y * inv;
                v[2] = v0.z * inv; v[3] = v0.w * inv;
                v[4] = v1.x * inv; v[5] = v1.y * inv;
                v[6] = v1.z * inv; v[7] = v1.w * inv;
            } else {
#pragma unroll
                for (int y = 0; y < 8; ++y) v[y] = 0.0f;
            }
            int nt = w >> 3, g = w & 7;
#pragma unroll
            for (int t = 0; t < 4; ++t) {
                sm[((ksg * 7 + nt) * 32 + g * 4 + t) * 2 + sel] =
                    pack_h2(v[2 * t], v[2 * t + 1]);
            }
        }
        __syncthreads();
        uint4* dst = reinterpret_cast<uint4*>(g_bq + (size_t)j * B_CAP_U32);
        const uint4* src = reinterpret_cast<const uint4*>(sm);
#pragma unroll
        for (int s = 0; s < B_CAP_U32 / 4 / 256; ++s)
            dst[tid + s * 256] = src[tid + s * 256];
    }
}

// ---------------------------------------------------------------------------
// m16n8k16 fp16 mma, fp32 accumulate
// ---------------------------------------------------------------------------
__device__ __forceinline__ void mma_f16(float* c, const uint4& a, const uint2& b) {
    asm volatile(
        "mma.sync.aligned.m16n8k16.row.col.f32.f16.f16.f32 "
        "{%0,%1,%2,%3}, {%4,%5,%6,%7}, {%8,%9}, {%0,%1,%2,%3};\n"
        : "+f"(c[0]), "+f"(c[1]), "+f"(c[2]), "+f"(c[3])
        : "r"(a.x), "r"(a.y), "r"(a.z), "r"(a.w), "r"(b.x), "r"(b.y));
}

// Stage one chunk: pure bulk copy, constant strides, zero index math.
__device__ __forceinline__ void stage(const uint32_t* srcA, uint32_t dstA,
                                      const uint32_t* srcB, uint32_t dstB) {
#pragma unroll
    for (int s = 0; s < 3; ++s)
        cp16(dstA + s * 2048, srcA + s * 512);
#pragma unroll
    for (int s = 0; s < 7; ++s)
        cp16(dstB + s * 1024, srcB + s * 256);
}

// ---------------------------------------------------------------------------
// Kernel 2: fused GEMM (fp16 mma.sync, cp.async double-buffered) + Sinkhorn.
// Block = IP imgs x JP caps; warp w owns pair (ii = w>>2, jj = w&3).
// ---------------------------------------------------------------------------
__global__ __launch_bounds__(256, 2)
void wass_kernel(const int* __restrict__ img_lens,
                 const int* __restrict__ cap_lens,
                 float* __restrict__ out) {
    extern __shared__ float smem[];
    uint32_t* sm32 = reinterpret_cast<uint32_t*>(smem);
    const int i0 = blockIdx.y * IP;
    const int j0 = blockIdx.x * JP;
    const int tid = threadIdx.x;
    const int lane = tid & 31;
    const int wid = tid >> 5;
    const int gid = lane >> 2;
    const int tig = lane & 3;
    const int ii = wid >> 2;
    const int jj = wid & 3;

    uint32_t sb;
    asm("{ .reg .u64 t; cvta.to.shared.u64 t, %1; cvt.u32.u64 %0, t; }"
        : "=r"(sb) : "l"(smem));

    // --- per-thread staging assignment (fixed for all chunks) ---
    const int imA = tid >> 7, tA = tid & 127;
    const int capB = tid >> 6, tB = tid & 63;
    const uint32_t* srcA = g_aq + (size_t)(i0 + imA) * A_IMG_U32 + tA * 4;
    const uint32_t* srcB = g_bq + (size_t)(j0 + capB) * B_CAP_U32 + tB * 4;
    const uint32_t dstA = sb + imA * (A_CHUNK_U32 * 4) + tA * 16;
    const uint32_t dstB = sb + A_REG_U32 * 4 + capB * (B_CHUNK_U32 * 4) + tB * 16;

    float C[MT][NT][4];
#pragma unroll
    for (int mt = 0; mt < MT; ++mt)
#pragma unroll
        for (int nt = 0; nt < NT; ++nt)
#pragma unroll
            for (int c = 0; c < 4; ++c) C[mt][nt][c] = 0.0f;

    // prologue: stage chunk 0 into buffer 0
    stage(srcA, dstA, srcB, dstB);
    asm volatile("cp.async.commit_group;" ::: "memory");
    const uint32_t* sA = srcA + A_CHUNK_U32;
    const uint32_t* sB = srcB + B_CHUNK_U32;

    for (int ch = 0; ch < NCHUNK; ++ch) {
        if (ch + 1 < NCHUNK) {
            uint32_t off = ((ch + 1) & 1) * BUF_BYTES;
            stage(sA, dstA + off, sB, dstB + off);
            asm volatile("cp.async.commit_group;" ::: "memory");
            sA += A_CHUNK_U32;
            sB += B_CHUNK_U32;
            asm volatile("cp.async.wait_group 1;" ::: "memory");
        } else {
            asm volatile("cp.async.wait_group 0;" ::: "memory");
        }
        __syncthreads();

        const uint4* Aq = reinterpret_cast<const uint4*>(
            sm32 + (ch & 1) * BUF_U32) + ii * (A_CHUNK_U32 / 4);
        const uint2* Bq = reinterpret_cast<const uint2*>(
            sm32 + (ch & 1) * BUF_U32 + A_REG_U32) + jj * (B_CHUNK_U32 / 2);
#pragma unroll
        for (int ks = 0; ks < NKS; ++ks) {
            uint4 a[MT];
#pragma unroll
            for (int mt = 0; mt < MT; ++mt)
                a[mt] = Aq[(ks * 3 + mt) * 32 + lane];       // one LDS.128
#pragma unroll
            for (int nt = 0; nt < NT; ++nt) {
                uint2 b = Bq[(ks * 7 + nt) * 32 + lane];     // one LDS.64
#pragma unroll
                for (int mt = 0; mt < MT; ++mt) mma_f16(C[mt][nt], a[mt], b);
            }
        }
        __syncthreads();   // buffer (ch&1) free for restage / Sinkhorn reuse
    }

    // ---------------- Sinkhorn (warp-private per pair) ----------------
    const int i = i0 + ii;
    const int j = j0 + jj;
    const int Ri = img_lens[i];
    const int Wj = cap_lens[j];
    float* Kp = smem + wid * KS_STRIDE;        // [36][57]
    float* alp = smem + AL_OFF + wid * RR;     // [36]
    float* bet = smem + BE_OFF + wid * WW;     // [50]

    // K = exp((s-1)/lambda) masked; accumulate total sum.
    // Ri/Wj are warp-uniform: tile-level guards are uniform branches.
    float tsum = 0.0f;
#pragma unroll
    for (int mt = 0; mt < MT; ++mt) {
        if (mt * 16 < Ri) {
#pragma unroll
            for (int nt = 0; nt < NT; ++nt) {
                if (nt * 8 < Wj) {
#pragma unroll
                    for (int c = 0; c < 4; ++c) {
                        int r = mt * 16 + gid + ((c >> 1) << 3);
                        int w = nt * 8 + (tig << 1) + (c & 1);
                        if (r < Ri && w < Wj) {
                            float s = C[mt][nt][c];
                            float k = __expf(ILAMB * s - ILAMB);
                            Kp[r * KW + w] = k;
                            tsum += k;
                        }
                    }
                }
            }
        }
    }
#pragma unroll
    for (int o = 16; o > 0; o >>= 1) tsum += __shfl_xor_sync(0xffffffffu, tsum, o);
    float alpha0 = 1.0f / (tsum + EPSV);

    for (int r = lane; r < Ri; r += 32) alp[r] = alpha0;
    for (int w = lane; w < Wj; w += 32) bet[w] = 1.0f;
    const float rm = 1.0f / (float)Ri;
    const float cm = 1.0f / (float)Wj;
    __syncwarp();

#pragma unroll
    for (int it = 0; it < 3; ++it) {
        for (int r = lane; r < Ri; r += 32) {
            float dot = 0.0f;
            for (int w = 0; w < Wj; ++w) dot += Kp[r * KW + w] * bet[w];
            float a = alp[r];
            alp[r] = a * (rm / (a * dot + EPSV));
        }
        __syncwarp();
        for (int w = lane; w < Wj; w += 32) {
            float dot = 0.0f;
            for (int r = 0; r < Ri; ++r) dot += Kp[r * KW + w] * alp[r];
            float b = bet[w];
            bet[w] = b * (cm / (b * dot + EPSV));
        }
        __syncwarp();
    }

    // final: sum s * K * alpha_r * beta_w; K re-read from smem (bit-identical)
    float acc = 0.0f;
#pragma unroll
    for (int mt = 0; mt < MT; ++mt) {
        if (mt * 16 < Ri) {
#pragma unroll
            for (int nt = 0; nt < NT; ++nt) {
                if (nt * 8 < Wj) {
#pragma unroll
                    for (int c = 0; c < 4; ++c) {
                        int r = mt * 16 + gid + ((c >> 1) << 3);
                        int w = nt * 8 + (tig << 1) + (c & 1);
                        if (r < Ri && w < Wj) {
                            float s = C[mt][nt][c];
                            float k = Kp[r * KW + w];
                            acc += s * k * alp[r] * bet[w];
                        }
                    }
                }
            }
        }
    }
#pragma unroll
    for (int o = 16; o > 0; o >>= 1) acc += __shfl_xor_sync(0xffffffffu, acc, o);
    if (lane == 0) out[i * BT + j] = acc;
}

// ---------------------------------------------------------------------------
extern "C" void kernel_launch(void* const* d_in, const int* in_sizes, int n_in,
                              void* d_out, int out_size) {
    const float* imgs = (const float*)d_in[0];
    const float* caps = (const float*)d_in[1];
    const int* img_lens = (const int*)d_in[2];
    const int* cap_lens = (const int*)d_in[3];
    float* out = (float*)d_out;

    cudaFuncSetAttribute(norm_kernel,
                         cudaFuncAttributeMaxDynamicSharedMemorySize, NORM_SMEM_BYTES);
    cudaFuncSetAttribute(wass_kernel,
                         cudaFuncAttributeMaxDynamicSharedMemorySize, SMEM_BYTES);

    norm_kernel<<<BI + BT, 256, NORM_SMEM_BYTES>>>(imgs, caps);

    dim3 grid(BT / JP, BI / IP);  // (32, 64)
    wass_kernel<<<grid, 256, SMEM_BYTES>>>(img_lens, cap_lens, out);
}